// round 5
// baseline (speedup 1.0000x reference)
#include <cuda_runtime.h>
#include <cuda_bf16.h>
#include <cstdint>

// ---------------- constants ----------------
#define TPB 256

// dConsts layout (float offsets)
#define C_B0   0      // 64
#define C_HS   64     // 80  hs[o*10+k]
#define C_HB   144    // 8
#define C_VPOS 152    // 64
#define C_WW2  216    // 640 Ww2[(g*10+k)*8+o]
#define C_BW2  856    // 80
#define C_B3   936    // 64
#define C_BOUT 1000   // 64
#define C_TOTAL 1064

// shared-memory layout (float offsets)
#define SM_XN   0        // 10240 : XN[m*160 + p*10 + k]
#define SM_FA   10240    // 10240 : F / pp / A / Y / Ov (time-multiplexed)
#define SM_WB   20480    // 5152  : W0T / Hmat(pad 644) / W3T / WoutT
#define SM_CST  25632    // 1064
#define SM_S    26696    // 160   : s[p*10+k]
#define SM_H    26856    // 128   : h[p*8+o]
#define SM_WV   26984    // 1280  : wv[p*80 + g*10 + k]
#define SM_SW   28264    // 128   : sw[p*8+g]
#define SM_FLOATS 28392
#define SMEM_BYTES (SM_FLOATS * 4)

__device__ float dW0T[4096];    // [c*64+m] = W0[m,c]
__device__ float dW3T[4096];    // [c*64+m] = W3[m,c]
__device__ float dWoutT[4096];  // [c*64+m] = Wout[m,c]
__device__ float dHmat[8 * 640];
__device__ float dConsts[C_TOTAL];

// ---------------------------------------------------------------------------
// Setup: fold weights.
//   vpos[m]  = sum_c Wp2[m,c]*relu(Wp1[c])         (valid since ptsn >= 0)
//   R[o][m]  = sum_k Ww1[o,m*10+k]
//   Hmat[o][c*10+k] = -sum_m Ww1[o,m*10+k]*W2[m,c] (+ sum_m R[o][m]*W1[m,c] @k==0)
//   hs[o][k] = sum_m Ww1[o,m*10+k]*vpos[m]
//   hb[o]    = sum_m R[o][m]*(b1[m]-b2[m])
// ---------------------------------------------------------------------------
__global__ void setup_kernel(const float* __restrict__ W0,  const float* __restrict__ b0,
                             const float* __restrict__ W1,  const float* __restrict__ b1,
                             const float* __restrict__ W2,  const float* __restrict__ b2,
                             const float* __restrict__ W3,  const float* __restrict__ b3,
                             const float* __restrict__ Wp1, const float* __restrict__ Wp2,
                             const float* __restrict__ Ww1, const float* __restrict__ Ww2,
                             const float* __restrict__ bw2, const float* __restrict__ Wout,
                             const float* __restrict__ bout)
{
    const int bid = blockIdx.x, tid = threadIdx.x;
    __shared__ float R[64], vp[64];
    if (bid < 8) {
        const int o = bid;
        if (tid < 64) {
            float r = 0.f;
            for (int k = 0; k < 10; ++k) r += Ww1[o*640 + tid*10 + k];
            R[tid] = r;
            float v = 0.f;
            for (int c = 0; c < 64; ++c) v += Wp2[tid*64 + c] * fmaxf(Wp1[c], 0.f);
            vp[tid] = v;
        }
        __syncthreads();
        for (int j = tid; j < 640; j += blockDim.x) {
            int c = j / 10, k = j - c*10;
            float v = 0.f;
            for (int m = 0; m < 64; ++m) v -= Ww1[o*640 + m*10 + k] * W2[m*64 + c];
            if (k == 0) {
                float w = 0.f;
                for (int m = 0; m < 64; ++m) w += R[m] * W1[m*64 + c];
                v += w;
            }
            dHmat[o*640 + j] = v;
        }
        if (tid == 0) {
            float v = 0.f;
            for (int m = 0; m < 64; ++m) v += R[m] * (b1[m] - b2[m]);
            dConsts[C_HB + o] = v;
        }
        if (tid < 10) {
            float v = 0.f;
            for (int m = 0; m < 64; ++m) v += Ww1[o*640 + m*10 + tid] * vp[m];
            dConsts[C_HS + o*10 + tid] = v;
        }
    } else if (bid == 8) {
        for (int i = tid; i < 4096; i += blockDim.x) dW0T[i] = W0[(i & 63)*64 + (i >> 6)];
    } else if (bid == 9) {
        for (int i = tid; i < 4096; i += blockDim.x) dW3T[i] = W3[(i & 63)*64 + (i >> 6)];
    } else if (bid == 10) {
        for (int i = tid; i < 4096; i += blockDim.x) dWoutT[i] = Wout[(i & 63)*64 + (i >> 6)];
    } else {
        if (tid < 64) {
            dConsts[C_B0 + tid]   = b0[tid];
            dConsts[C_B3 + tid]   = b3[tid];
            dConsts[C_BOUT + tid] = bout[tid];
            float v = 0.f;
            for (int c = 0; c < 64; ++c) v += Wp2[tid*64 + c] * fmaxf(Wp1[c], 0.f);
            dConsts[C_VPOS + tid] = v;
        }
        for (int i = tid; i < 640; i += blockDim.x) dConsts[C_WW2 + i] = Ww2[i];
        for (int i = tid; i < 80;  i += blockDim.x) dConsts[C_BW2 + i] = bw2[i];
    }
}

// ---------------------------------------------------------------------------
// Main fused kernel: 16 points per block, 256 threads, 4096 blocks.
// ---------------------------------------------------------------------------
__global__ void __launch_bounds__(TPB, 2)
pt_main(const float* __restrict__ feats, const float* __restrict__ cent,
        const float* __restrict__ smp, float* __restrict__ out)
{
    extern __shared__ float sm[];
    const int tid = threadIdx.x;
    const int b   = blockIdx.x >> 9;           // 512 blocks per batch
    const int n0  = (blockIdx.x & 511) << 4;

    float* XN  = sm + SM_XN;
    float* FA  = sm + SM_FA;
    float* WB  = sm + SM_WB;
    float* cst = sm + SM_CST;
    float* S   = sm + SM_S;
    float* H   = sm + SM_H;
    float* WV  = sm + SM_WV;
    float* SW  = sm + SM_SW;

    // ---- phase 0: loads: F (feats tile), W0T, consts, s ----
    {
        float* F = FA;
        for (int i = tid; i < 2560; i += TPB) {
            int c = i / 40, q = i - c*40;
            const float4 v = __ldg(reinterpret_cast<const float4*>(
                                       feats + ((size_t)(b*64 + c)*8192 + n0)*10) + q);
            *reinterpret_cast<float4*>(&F[c*160 + q*4]) = v;
        }
        for (int i = tid; i < 1024; i += TPB)
            reinterpret_cast<float4*>(WB)[i] = reinterpret_cast<const float4*>(dW0T)[i];
        for (int i = tid; i < C_TOTAL; i += TPB) cst[i] = dConsts[i];
        if (tid < 160) {
            int p = tid / 10, k = tid - p*10;
            int n = n0 + p;
            float c0 = __ldg(&cent[((size_t)b*8192 + n)*3 + 0]);
            float c1 = __ldg(&cent[((size_t)b*8192 + n)*3 + 1]);
            float c2 = __ldg(&cent[((size_t)b*8192 + n)*3 + 2]);
            float d0 = c0 - __ldg(&smp[(((size_t)b*3 + 0)*8192 + n)*10 + k]);
            float d1 = c1 - __ldg(&smp[(((size_t)b*3 + 1)*8192 + n)*10 + k]);
            float d2 = c2 - __ldg(&smp[(((size_t)b*3 + 2)*8192 + n)*10 + k]);
            S[tid] = d0*d0 + d1*d1 + d2*d2;
        }
    }
    __syncthreads();

    // ---- phase 1: XN[m][col] = relu(sum_c W0[m,c]*F[c][col] + b0[m]) ----
    // col = p*10+k (160 cols). 8 m-groups x 32 col-groups of 5.
    {
        const float* F = FA;
        const int mg = tid & 7, cg = tid >> 3;
        const int m0 = mg * 8, col0 = cg * 5;
        float acc[8][5];
        #pragma unroll
        for (int i = 0; i < 8; ++i)
            #pragma unroll
            for (int j = 0; j < 5; ++j) acc[i][j] = 0.f;
        #pragma unroll 4
        for (int c = 0; c < 64; ++c) {
            float4 wa = *reinterpret_cast<const float4*>(&WB[c*64 + m0]);
            float4 wb = *reinterpret_cast<const float4*>(&WB[c*64 + m0 + 4]);
            float w[8] = {wa.x, wa.y, wa.z, wa.w, wb.x, wb.y, wb.z, wb.w};
            float f[5];
            #pragma unroll
            for (int j = 0; j < 5; ++j) f[j] = F[c*160 + col0 + j];
            #pragma unroll
            for (int i = 0; i < 8; ++i)
                #pragma unroll
                for (int j = 0; j < 5; ++j)
                    acc[i][j] = fmaf(w[i], f[j], acc[i][j]);
        }
        #pragma unroll
        for (int j = 0; j < 5; ++j) {
            int col = col0 + j;
            #pragma unroll
            for (int i = 0; i < 8; ++i)
                XN[(m0 + i)*160 + col] = fmaxf(acc[i][j] + cst[C_B0 + m0 + i], 0.f);
        }
    }
    __syncthreads();

    // ---- load Hmat into WB, padded stride 644 (bank-conflict avoidance) ----
    for (int i = tid; i < 5120; i += TPB) {
        int o = i / 640, j = i - o*640;
        WB[o*644 + j] = dHmat[i];
    }
    __syncthreads();

    // ---- phase 2: h[p][o] = relu(Hmat[o,:] . XN[:,p,:] + hs.s + hb) ----
    {
        float* pp = FA;
        const int po = tid >> 1, half = tid & 1;
        const int p = po >> 3, o = po & 7;
        const float* Hrow = &WB[o*644 + half*320];
        const float* Xp   = &XN[p*10];
        float v = 0.f;
        #pragma unroll 4
        for (int ci = 0; ci < 32; ++ci) {
            const int c = half*32 + ci;
            #pragma unroll
            for (int k = 0; k < 10; ++k)
                v = fmaf(Hrow[ci*10 + k], Xp[c*160 + k], v);
        }
        pp[tid] = v;
        __syncthreads();
        if (tid < 128) {
            const int p2 = tid >> 3, o2 = tid & 7;
            float h = pp[2*tid] + pp[2*tid + 1] + cst[C_HB + o2];
            #pragma unroll
            for (int k = 0; k < 10; ++k)
                h = fmaf(cst[C_HS + o2*10 + k], S[p2*10 + k], h);
            H[p2*8 + o2] = fmaxf(h, 0.f);
        }
    }
    __syncthreads();

    // ---- phase 3a: wv[p][g*10+k] = Ww2 @ h + bw2 ----
    for (int idx = tid; idx < 1280; idx += TPB) {
        int p = idx / 80, r = idx - p*80;
        float v = cst[C_BW2 + r];
        #pragma unroll
        for (int o = 0; o < 8; ++o)
            v = fmaf(cst[C_WW2 + r*8 + o], H[p*8 + o], v);
        WV[idx] = v;
    }
    __syncthreads();

    // ---- phase 3b: softmax over k; sw[p][g] = sum_k w*s. Also load W3T. ----
    if (tid < 128) {
        const int p = tid >> 3, g = tid & 7;
        float* wrow = &WV[p*80 + g*10];
        float mx = wrow[0];
        #pragma unroll
        for (int k = 1; k < 10; ++k) mx = fmaxf(mx, wrow[k]);
        float e[10], sum = 0.f;
        #pragma unroll
        for (int k = 0; k < 10; ++k) { e[k] = __expf(wrow[k] - mx); sum += e[k]; }
        const float inv = 1.f / sum;
        float swv = 0.f;
        #pragma unroll
        for (int k = 0; k < 10; ++k) {
            float w = e[k] * inv;
            wrow[k] = w;
            swv = fmaf(w, S[p*10 + k], swv);
        }
        SW[p*8 + g] = swv;
    }
    for (int i = tid; i < 4096; i += TPB) WB[i] = dW3T[i];
    __syncthreads();

    // ---- phase 4: A[c][p*8+g] = sum_k w[p,g,k]*XN[c][p*10+k] ----
    {
        float* A = FA;
        for (int idx = tid; idx < 8192; idx += TPB) {
            int c = idx >> 7, r = idx & 127;
            int p = r >> 3, g = r & 7;
            const float* wr = &WV[p*80 + g*10];
            const float* xr = &XN[c*160 + p*10];
            float v = 0.f;
            #pragma unroll
            for (int k = 0; k < 10; ++k) v = fmaf(wr[k], xr[k], v);
            A[idx] = v;
        }
    }
    __syncthreads();

    // ---- phase 5: y[p][m] = relu(sum_c W3[m,c]*A[c,p,m&7] + b3 + vpos*sw) ----
    {
        const float* A = FA;
        float* Y = FA + 8192;           // stride 66
        const int m = tid & 63, pq = tid >> 6, g = m & 7;
        float acc[4] = {0.f, 0.f, 0.f, 0.f};
        #pragma unroll 4
        for (int c = 0; c < 64; ++c) {
            const float w3 = WB[c*64 + m];
            #pragma unroll
            for (int pi = 0; pi < 4; ++pi)
                acc[pi] = fmaf(w3, A[c*128 + (pq*4 + pi)*8 + g], acc[pi]);
        }
        #pragma unroll
        for (int pi = 0; pi < 4; ++pi) {
            const int p = pq*4 + pi;
            Y[p*66 + m] = fmaxf(acc[pi] + cst[C_B3 + m] + cst[C_VPOS + m]*SW[p*8 + g], 0.f);
        }
    }
    __syncthreads();

    // ---- load WoutT ----
    for (int i = tid; i < 4096; i += TPB) WB[i] = dWoutT[i];
    __syncthreads();

    // ---- phase 6: out[p][m] = Wout@y + bout + xn[m,p,0] -> Ov[m*16+p] ----
    {
        const float* Y = FA + 8192;
        float* Ov = FA;                 // A is dead; disjoint from Y
        const int m = tid & 63, pq = tid >> 6;
        float acc[4] = {0.f, 0.f, 0.f, 0.f};
        #pragma unroll 4
        for (int c = 0; c < 64; ++c) {
            const float wo = WB[c*64 + m];
            #pragma unroll
            for (int pi = 0; pi < 4; ++pi)
                acc[pi] = fmaf(wo, Y[(pq*4 + pi)*66 + c], acc[pi]);
        }
        #pragma unroll
        for (int pi = 0; pi < 4; ++pi) {
            const int p = pq*4 + pi;
            Ov[m*16 + p] = acc[pi] + cst[C_BOUT + m] + XN[m*160 + p*10];
        }
    }
    __syncthreads();

    // ---- staged coalesced store: out[(b*64+m)*8192 + n0 + q*4 .. +3] ----
    {
        const float* Ov = FA;
        const int m = tid >> 2, q = tid & 3;
        float4 v = *reinterpret_cast<const float4*>(&Ov[m*16 + q*4]);
        *reinterpret_cast<float4*>(&out[((size_t)b*64 + m)*8192 + n0 + q*4]) = v;
    }
}

// ---------------------------------------------------------------------------
extern "C" void kernel_launch(void* const* d_in, const int* in_sizes, int n_in,
                              void* d_out, int out_size)
{
    const float* feats = (const float*)d_in[0];   // (8,64,8192,10)
    const float* cent  = (const float*)d_in[1];   // (8,8192,3)
    const float* smp   = (const float*)d_in[2];   // (8,3,8192,10)
    const float* W0    = (const float*)d_in[3];
    const float* b0    = (const float*)d_in[4];
    const float* W1    = (const float*)d_in[5];
    const float* b1    = (const float*)d_in[6];
    const float* W2    = (const float*)d_in[7];
    const float* b2    = (const float*)d_in[8];
    const float* W3    = (const float*)d_in[9];
    const float* b3    = (const float*)d_in[10];
    const float* Wp1   = (const float*)d_in[11];
    const float* Wp2   = (const float*)d_in[12];
    const float* Ww1   = (const float*)d_in[13];
    const float* Ww2   = (const float*)d_in[14];
    const float* bw2   = (const float*)d_in[15];
    const float* Wout  = (const float*)d_in[16];
    const float* bout  = (const float*)d_in[17];
    float* out = (float*)d_out;

    cudaFuncSetAttribute(pt_main, cudaFuncAttributeMaxDynamicSharedMemorySize, SMEM_BYTES);

    setup_kernel<<<12, 256>>>(W0, b0, W1, b1, W2, b2, W3, b3,
                              Wp1, Wp2, Ww1, Ww2, bw2, Wout, bout);
    pt_main<<<4096, TPB, SMEM_BYTES>>>(feats, cent, smp, out);
}

// round 6
// speedup vs baseline: 1.0079x; 1.0079x over previous
#include <cuda_runtime.h>
#include <cuda_bf16.h>
#include <cstdint>

// ---------------- constants ----------------
#define TPB 256

// dConsts layout (float offsets)
#define C_B0   0      // 64
#define C_HS   64     // 80  hs[o*10+k]
#define C_HB   144    // 8
#define C_VPOS 152    // 64
#define C_WW2  216    // 640 Ww2[(g*10+k)*8+o]
#define C_BW2  856    // 80
#define C_B3   936    // 64
#define C_BOUT 1000   // 64
#define C_TOTAL 1064

// shared-memory layout (float offsets)
#define SM_XN   0        // 10240 : XN[m*160 + p*10 + k]
#define SM_FA   10240    // 10240 : F / pp / A / Y / Ov (time-multiplexed)
#define SM_WB   20480    // 5152  : W0T / Hmat(pad 644) / W3T / WoutT
#define SM_CST  25632    // 1064
#define SM_S    26696    // 160   : s[p*10+k]
#define SM_H    26856    // 128   : h[p*8+o]
#define SM_WV   26984    // 1280  : wv[p*80 + g*10 + k]
#define SM_SW   28264    // 128   : sw[p*8+g]
#define SM_FLOATS 28392
#define SMEM_BYTES (SM_FLOATS * 4)

__device__ float dW0T[4096];    // [c*64+m] = W0[m,c]
__device__ float dW3T[4096];    // [c*64+m] = W3[m,c]
__device__ float dWoutT[4096];  // [c*64+m] = Wout[m,c]
__device__ float dHmat[8 * 640];
__device__ float dConsts[C_TOTAL];

// ---------------------------------------------------------------------------
// Setup: fold weights.
//   vpos[m]  = sum_c Wp2[m,c]*relu(Wp1[c])         (valid since ptsn >= 0)
//   R[o][m]  = sum_k Ww1[o,m*10+k]
//   Hmat[o][c*10+k] = -sum_m Ww1[o,m*10+k]*W2[m,c] (+ sum_m R[o][m]*W1[m,c] @k==0)
//   hs[o][k] = sum_m Ww1[o,m*10+k]*vpos[m]
//   hb[o]    = sum_m R[o][m]*(b1[m]-b2[m])
// ---------------------------------------------------------------------------
__global__ void setup_kernel(const float* __restrict__ W0,  const float* __restrict__ b0,
                             const float* __restrict__ W1,  const float* __restrict__ b1,
                             const float* __restrict__ W2,  const float* __restrict__ b2,
                             const float* __restrict__ W3,  const float* __restrict__ b3,
                             const float* __restrict__ Wp1, const float* __restrict__ Wp2,
                             const float* __restrict__ Ww1, const float* __restrict__ Ww2,
                             const float* __restrict__ bw2, const float* __restrict__ Wout,
                             const float* __restrict__ bout)
{
    const int bid = blockIdx.x, tid = threadIdx.x;
    __shared__ float R[64], vp[64];
    if (bid < 8) {
        const int o = bid;
        if (tid < 64) {
            float r = 0.f;
            for (int k = 0; k < 10; ++k) r += Ww1[o*640 + tid*10 + k];
            R[tid] = r;
            float v = 0.f;
            for (int c = 0; c < 64; ++c) v += Wp2[tid*64 + c] * fmaxf(Wp1[c], 0.f);
            vp[tid] = v;
        }
        __syncthreads();
        for (int j = tid; j < 640; j += blockDim.x) {
            int c = j / 10, k = j - c*10;
            float v = 0.f;
            for (int m = 0; m < 64; ++m) v -= Ww1[o*640 + m*10 + k] * W2[m*64 + c];
            if (k == 0) {
                float w = 0.f;
                for (int m = 0; m < 64; ++m) w += R[m] * W1[m*64 + c];
                v += w;
            }
            dHmat[o*640 + j] = v;
        }
        if (tid == 0) {
            float v = 0.f;
            for (int m = 0; m < 64; ++m) v += R[m] * (b1[m] - b2[m]);
            dConsts[C_HB + o] = v;
        }
        if (tid < 10) {
            float v = 0.f;
            for (int m = 0; m < 64; ++m) v += Ww1[o*640 + m*10 + tid] * vp[m];
            dConsts[C_HS + o*10 + tid] = v;
        }
    } else if (bid == 8) {
        for (int i = tid; i < 4096; i += blockDim.x) dW0T[i] = W0[(i & 63)*64 + (i >> 6)];
    } else if (bid == 9) {
        for (int i = tid; i < 4096; i += blockDim.x) dW3T[i] = W3[(i & 63)*64 + (i >> 6)];
    } else if (bid == 10) {
        for (int i = tid; i < 4096; i += blockDim.x) dWoutT[i] = Wout[(i & 63)*64 + (i >> 6)];
    } else {
        if (tid < 64) {
            dConsts[C_B0 + tid]   = b0[tid];
            dConsts[C_B3 + tid]   = b3[tid];
            dConsts[C_BOUT + tid] = bout[tid];
            float v = 0.f;
            for (int c = 0; c < 64; ++c) v += Wp2[tid*64 + c] * fmaxf(Wp1[c], 0.f);
            dConsts[C_VPOS + tid] = v;
        }
        for (int i = tid; i < 640; i += blockDim.x) dConsts[C_WW2 + i] = Ww2[i];
        for (int i = tid; i < 80;  i += blockDim.x) dConsts[C_BW2 + i] = bw2[i];
    }
}

// ---------------------------------------------------------------------------
// Main fused kernel: 16 points per block, 256 threads, 4096 blocks.
// ---------------------------------------------------------------------------
__global__ void __launch_bounds__(TPB, 2)
pt_main(const float* __restrict__ feats, const float* __restrict__ cent,
        const float* __restrict__ smp, float* __restrict__ out)
{
    extern __shared__ float sm[];
    const int tid = threadIdx.x;
    const int b   = blockIdx.x >> 9;           // 512 blocks per batch
    const int n0  = (blockIdx.x & 511) << 4;

    float* XN  = sm + SM_XN;
    float* FA  = sm + SM_FA;
    float* WB  = sm + SM_WB;
    float* cst = sm + SM_CST;
    float* S   = sm + SM_S;
    float* H   = sm + SM_H;
    float* WV  = sm + SM_WV;
    float* SW  = sm + SM_SW;

    // ---- phase 0: loads: F (feats tile), W0T, consts, s ----
    {
        float* F = FA;
        for (int i = tid; i < 2560; i += TPB) {
            int c = i / 40, q = i - c*40;
            const float4 v = __ldg(reinterpret_cast<const float4*>(
                                       feats + ((size_t)(b*64 + c)*8192 + n0)*10) + q);
            *reinterpret_cast<float4*>(&F[c*160 + q*4]) = v;
        }
        for (int i = tid; i < 1024; i += TPB)
            reinterpret_cast<float4*>(WB)[i] = reinterpret_cast<const float4*>(dW0T)[i];
        for (int i = tid; i < C_TOTAL; i += TPB) cst[i] = dConsts[i];
        if (tid < 160) {
            int p = tid / 10, k = tid - p*10;
            int n = n0 + p;
            float c0 = __ldg(&cent[((size_t)b*8192 + n)*3 + 0]);
            float c1 = __ldg(&cent[((size_t)b*8192 + n)*3 + 1]);
            float c2 = __ldg(&cent[((size_t)b*8192 + n)*3 + 2]);
            float d0 = c0 - __ldg(&smp[(((size_t)b*3 + 0)*8192 + n)*10 + k]);
            float d1 = c1 - __ldg(&smp[(((size_t)b*3 + 1)*8192 + n)*10 + k]);
            float d2 = c2 - __ldg(&smp[(((size_t)b*3 + 2)*8192 + n)*10 + k]);
            S[tid] = d0*d0 + d1*d1 + d2*d2;
        }
    }
    __syncthreads();

    // ---- phase 1: XN[m][col] = relu(sum_c W0[m,c]*F[c][col] + b0[m]) ----
    // col = p*10+k (160 cols). 8 m-groups x 32 col-groups of 5.
    {
        const float* F = FA;
        const int mg = tid & 7, cg = tid >> 3;
        const int m0 = mg * 8, col0 = cg * 5;
        float acc[8][5];
        #pragma unroll
        for (int i = 0; i < 8; ++i)
            #pragma unroll
            for (int j = 0; j < 5; ++j) acc[i][j] = 0.f;
        #pragma unroll 4
        for (int c = 0; c < 64; ++c) {
            float4 wa = *reinterpret_cast<const float4*>(&WB[c*64 + m0]);
            float4 wb = *reinterpret_cast<const float4*>(&WB[c*64 + m0 + 4]);
            float w[8] = {wa.x, wa.y, wa.z, wa.w, wb.x, wb.y, wb.z, wb.w};
            float f[5];
            #pragma unroll
            for (int j = 0; j < 5; ++j) f[j] = F[c*160 + col0 + j];
            #pragma unroll
            for (int i = 0; i < 8; ++i)
                #pragma unroll
                for (int j = 0; j < 5; ++j)
                    acc[i][j] = fmaf(w[i], f[j], acc[i][j]);
        }
        #pragma unroll
        for (int j = 0; j < 5; ++j) {
            int col = col0 + j;
            #pragma unroll
            for (int i = 0; i < 8; ++i)
                XN[(m0 + i)*160 + col] = fmaxf(acc[i][j] + cst[C_B0 + m0 + i], 0.f);
        }
    }
    __syncthreads();

    // ---- load Hmat into WB, padded stride 644 (bank-conflict avoidance) ----
    for (int i = tid; i < 5120; i += TPB) {
        int o = i / 640, j = i - o*640;
        WB[o*644 + j] = dHmat[i];
    }
    __syncthreads();

    // ---- phase 2: h[p][o] = relu(Hmat[o,:] . XN[:,p,:] + hs.s + hb) ----
    {
        float* pp = FA;
        const int po = tid >> 1, half = tid & 1;
        const int p = po >> 3, o = po & 7;
        const float* Hrow = &WB[o*644 + half*320];
        const float* Xp   = &XN[p*10];
        float v = 0.f;
        #pragma unroll 4
        for (int ci = 0; ci < 32; ++ci) {
            const int c = half*32 + ci;
            #pragma unroll
            for (int k = 0; k < 10; ++k)
                v = fmaf(Hrow[ci*10 + k], Xp[c*160 + k], v);
        }
        pp[tid] = v;
        __syncthreads();
        if (tid < 128) {
            const int p2 = tid >> 3, o2 = tid & 7;
            float h = pp[2*tid] + pp[2*tid + 1] + cst[C_HB + o2];
            #pragma unroll
            for (int k = 0; k < 10; ++k)
                h = fmaf(cst[C_HS + o2*10 + k], S[p2*10 + k], h);
            H[p2*8 + o2] = fmaxf(h, 0.f);
        }
    }
    __syncthreads();

    // ---- phase 3a: wv[p][g*10+k] = Ww2 @ h + bw2 ----
    for (int idx = tid; idx < 1280; idx += TPB) {
        int p = idx / 80, r = idx - p*80;
        float v = cst[C_BW2 + r];
        #pragma unroll
        for (int o = 0; o < 8; ++o)
            v = fmaf(cst[C_WW2 + r*8 + o], H[p*8 + o], v);
        WV[idx] = v;
    }
    __syncthreads();

    // ---- phase 3b: softmax over k; sw[p][g] = sum_k w*s. Also load W3T. ----
    if (tid < 128) {
        const int p = tid >> 3, g = tid & 7;
        float* wrow = &WV[p*80 + g*10];
        float mx = wrow[0];
        #pragma unroll
        for (int k = 1; k < 10; ++k) mx = fmaxf(mx, wrow[k]);
        float e[10], sum = 0.f;
        #pragma unroll
        for (int k = 0; k < 10; ++k) { e[k] = __expf(wrow[k] - mx); sum += e[k]; }
        const float inv = 1.f / sum;
        float swv = 0.f;
        #pragma unroll
        for (int k = 0; k < 10; ++k) {
            float w = e[k] * inv;
            wrow[k] = w;
            swv = fmaf(w, S[p*10 + k], swv);
        }
        SW[p*8 + g] = swv;
    }
    for (int i = tid; i < 4096; i += TPB) WB[i] = dW3T[i];
    __syncthreads();

    // ---- phase 4: A[c][p*8+g] = sum_k w[p,g,k]*XN[c][p*10+k] ----
    {
        float* A = FA;
        for (int idx = tid; idx < 8192; idx += TPB) {
            int c = idx >> 7, r = idx & 127;
            int p = r >> 3, g = r & 7;
            const float* wr = &WV[p*80 + g*10];
            const float* xr = &XN[c*160 + p*10];
            float v = 0.f;
            #pragma unroll
            for (int k = 0; k < 10; ++k) v = fmaf(wr[k], xr[k], v);
            A[idx] = v;
        }
    }
    __syncthreads();

    // ---- phase 5: y[p][m] = relu(sum_c W3[m,c]*A[c,p,m&7] + b3 + vpos*sw) ----
    {
        const float* A = FA;
        float* Y = FA + 8192;           // stride 66
        const int m = tid & 63, pq = tid >> 6, g = m & 7;
        float acc[4] = {0.f, 0.f, 0.f, 0.f};
        #pragma unroll 4
        for (int c = 0; c < 64; ++c) {
            const float w3 = WB[c*64 + m];
            #pragma unroll
            for (int pi = 0; pi < 4; ++pi)
                acc[pi] = fmaf(w3, A[c*128 + (pq*4 + pi)*8 + g], acc[pi]);
        }
        #pragma unroll
        for (int pi = 0; pi < 4; ++pi) {
            const int p = pq*4 + pi;
            Y[p*66 + m] = fmaxf(acc[pi] + cst[C_B3 + m] + cst[C_VPOS + m]*SW[p*8 + g], 0.f);
        }
    }
    __syncthreads();

    // ---- load WoutT ----
    for (int i = tid; i < 4096; i += TPB) WB[i] = dWoutT[i];
    __syncthreads();

    // ---- phase 6: out[p][m] = Wout@y + bout + xn[m,p,0] -> Ov[m*16+p] ----
    {
        const float* Y = FA + 8192;
        float* Ov = FA;                 // A is dead; disjoint from Y
        const int m = tid & 63, pq = tid >> 6;
        float acc[4] = {0.f, 0.f, 0.f, 0.f};
        #pragma unroll 4
        for (int c = 0; c < 64; ++c) {
            const float wo = WB[c*64 + m];
            #pragma unroll
            for (int pi = 0; pi < 4; ++pi)
                acc[pi] = fmaf(wo, Y[(pq*4 + pi)*66 + c], acc[pi]);
        }
        #pragma unroll
        for (int pi = 0; pi < 4; ++pi) {
            const int p = pq*4 + pi;
            Ov[m*16 + p] = acc[pi] + cst[C_BOUT + m] + XN[m*160 + p*10];
        }
    }
    __syncthreads();

    // ---- staged coalesced store: out[(b*64+m)*8192 + n0 + q*4 .. +3] ----
    {
        const float* Ov = FA;
        const int m = tid >> 2, q = tid & 3;
        float4 v = *reinterpret_cast<const float4*>(&Ov[m*16 + q*4]);
        *reinterpret_cast<float4*>(&out[((size_t)b*64 + m)*8192 + n0 + q*4]) = v;
    }
}

// ---------------------------------------------------------------------------
extern "C" void kernel_launch(void* const* d_in, const int* in_sizes, int n_in,
                              void* d_out, int out_size)
{
    const float* feats = (const float*)d_in[0];   // (8,64,8192,10)
    const float* cent  = (const float*)d_in[1];   // (8,8192,3)
    const float* smp   = (const float*)d_in[2];   // (8,3,8192,10)
    const float* W0    = (const float*)d_in[3];
    const float* b0    = (const float*)d_in[4];
    const float* W1    = (const float*)d_in[5];
    const float* b1    = (const float*)d_in[6];
    const float* W2    = (const float*)d_in[7];
    const float* b2    = (const float*)d_in[8];
    const float* W3    = (const float*)d_in[9];
    const float* b3    = (const float*)d_in[10];
    const float* Wp1   = (const float*)d_in[11];
    const float* Wp2   = (const float*)d_in[12];
    const float* Ww1   = (const float*)d_in[13];
    const float* Ww2   = (const float*)d_in[14];
    const float* bw2   = (const float*)d_in[15];
    const float* Wout  = (const float*)d_in[16];
    const float* bout  = (const float*)d_in[17];
    float* out = (float*)d_out;

    cudaFuncSetAttribute(pt_main, cudaFuncAttributeMaxDynamicSharedMemorySize, SMEM_BYTES);

    setup_kernel<<<12, 256>>>(W0, b0, W1, b1, W2, b2, W3, b3,
                              Wp1, Wp2, Ww1, Ww2, bw2, Wout, bout);
    pt_main<<<4096, TPB, SMEM_BYTES>>>(feats, cent, smp, out);
}